// round 13
// baseline (speedup 1.0000x reference)
#include <cuda_runtime.h>
#include <cuda_fp16.h>
#include <cstdint>
#include <cstddef>

#define BATCH   4
#define DIMC    384
#define HEADS   8
#define DHEAD   64
#define INNER   512
#define QKV_CH  1536
#define IMG_H   56
#define IMG_W   56
#define HW      3136
#define NPIX    (BATCH * HW)      // 12544
#define SCALE   0.125f

#define K1      384               // GEMM1: plain fp16
#define K2      512               // GEMM2: plain fp16

// Scratch (device globals; allocation forbidden)
__device__ __half g_xT  [(size_t)NPIX * K1];      // A1: hi of x, pixel-major
__device__ __half g_wqkv[(size_t)QKV_CH * DIMC];  // B1: hi
__device__ __half g_wo  [(size_t)DIMC * K2];      // A2: hi of Wo
__device__ __half g_qkvT[(size_t)NPIX * QKV_CH];  // pixel-major q|k|v (fp16)
__device__ __half g_aoT [(size_t)NPIX * INNER];   // B2: hi

// ---------------- PTX helpers (baseline sm_80+ features only) ----------------
__device__ __forceinline__ uint32_t smem_u32(const void* p) {
    uint32_t a;
    asm("{ .reg .u64 t; cvta.to.shared.u64 t, %1; cvt.u32.u64 %0, t; }" : "=r"(a) : "l"(p));
    return a;
}
__device__ __forceinline__ void cp_async16(uint32_t saddr, const void* gptr) {
    asm volatile("cp.async.cg.shared.global [%0], [%1], 16;\n" :: "r"(saddr), "l"(gptr));
}
__device__ __forceinline__ void cp_commit() {
    asm volatile("cp.async.commit_group;\n" ::: "memory");
}
template <int N> __device__ __forceinline__ void cp_wait() {
    asm volatile("cp.async.wait_group %0;\n" :: "n"(N) : "memory");
}
__device__ __forceinline__ void ldsm_x4(uint32_t addr, uint32_t& r0, uint32_t& r1,
                                        uint32_t& r2, uint32_t& r3) {
    asm volatile("ldmatrix.sync.aligned.m8n8.x4.shared.b16 {%0,%1,%2,%3}, [%4];"
                 : "=r"(r0), "=r"(r1), "=r"(r2), "=r"(r3) : "r"(addr));
}
__device__ __forceinline__ void mma16816(float* d, const uint32_t* a, const uint32_t* b) {
    asm volatile("mma.sync.aligned.m16n8k16.row.col.f32.f16.f16.f32 "
        "{%0,%1,%2,%3}, {%4,%5,%6,%7}, {%8,%9}, {%0,%1,%2,%3};"
        : "+f"(d[0]), "+f"(d[1]), "+f"(d[2]), "+f"(d[3])
        : "r"(a[0]), "r"(a[1]), "r"(a[2]), "r"(a[3]), "r"(b[0]), "r"(b[1]));
}

// ---------------- input converts ----------------
__global__ __launch_bounds__(256) void transpose_convert(
    const float* __restrict__ x, __half* __restrict__ xT)
{
    __shared__ float t[32][33];
    const int p0 = blockIdx.x * 32, c0 = blockIdx.y * 32, b = blockIdx.z;
    const int tx = threadIdx.x, ty = threadIdx.y;
    const float* src = x + (size_t)b * DIMC * HW;
    #pragma unroll
    for (int i = 0; i < 32; i += 8)
        t[ty + i][tx] = src[(size_t)(c0 + ty + i) * HW + p0 + tx];
    __syncthreads();
    __half* dst = xT + (size_t)b * HW * K1;
    #pragma unroll
    for (int i = 0; i < 32; i += 8) {
        const size_t row = (size_t)(p0 + ty + i) * K1;
        dst[row + c0 + tx] = __float2half(t[tx][ty + i]);
    }
}

// Merged weight converts: blocks [0,1536) -> wqkv hi; [1536,1920) -> wo hi
__global__ __launch_bounds__(512) void weights_convert(
    const float* __restrict__ Wq, const float* __restrict__ Wkv,
    const float* __restrict__ Wo,
    __half* __restrict__ wqkv, __half* __restrict__ wo)
{
    const int blk = blockIdx.x;
    const int k = threadIdx.x;
    if (blk < QKV_CH) {
        if (k < DIMC) {
            const float w = (blk < INNER) ? Wq[(size_t)blk * DIMC + k]
                                          : Wkv[(size_t)(blk - INNER) * DIMC + k];
            wqkv[(size_t)blk * DIMC + k] = __float2half(w);
        }
    } else {
        const int row = blk - QKV_CH;
        wo[(size_t)row * K2 + k] = __float2half(Wo[(size_t)row * INNER + k]);
    }
}

// ---------------- mma.sync fp16 GEMM ----------------
// D[m][n] = sum_k A[m][k]*B[n][k]; CTA tile 128x256, K-chunk 64, 3-stage cp.async.
// 8 warps 2(M)x4(N), warp 64x64. EPI 0: C __half*, row-major ldc.
// EPI 1: C float*, channel-major + bias.
#define STG 49152   // per stage: A 128*128B (16KB) + B 256*128B (32KB)

__device__ __forceinline__ void stage_ld(uint32_t sA, uint32_t sB,
    const __half* __restrict__ Ag, int lda,
    const __half* __restrict__ Bg, int ldb, int kt, int tid)
{
    #pragma unroll
    for (int i = 0; i < 4; i++) {
        const int idx = tid + i * 256;
        const int row = idx >> 3, j = idx & 7;
        const uint32_t off = (uint32_t)(row * 128 + ((j ^ (row & 7)) * 16));
        cp_async16(sA + off, Ag + (size_t)row * lda + kt + j * 8);
    }
    #pragma unroll
    for (int i = 0; i < 8; i++) {
        const int idx = tid + i * 256;
        const int row = idx >> 3, j = idx & 7;
        const uint32_t off = (uint32_t)(row * 128 + ((j ^ (row & 7)) * 16));
        cp_async16(sB + off, Bg + (size_t)row * ldb + kt + j * 8);
    }
}

template <int T, int EPI>
__global__ __launch_bounds__(256) void hmma_gemm(
    const __half* __restrict__ A, int lda,
    const __half* __restrict__ B, int ldb,
    const float* __restrict__ bias, void* __restrict__ C, int ldc)
{
    extern __shared__ char dynraw[];
    const uint32_t smem = smem_u32(dynraw);
    const int tid = threadIdx.x;
    const int w = tid >> 5, l = tid & 31;
    const int wm = w >> 2, wn = w & 3;
    const int n0 = blockIdx.x * 256, m0 = blockIdx.y * 128;

    const __half* Ag = A + (size_t)m0 * lda;
    const __half* Bg = B + (size_t)n0 * ldb;

    float acc[4][8][4];
    #pragma unroll
    for (int i = 0; i < 4; i++)
        #pragma unroll
        for (int j = 0; j < 8; j++)
            #pragma unroll
            for (int c = 0; c < 4; c++) acc[i][j][c] = 0.f;

    // ldmatrix lane constants (all non-trans; K-major operands)
    const int arow_l = (l & 7) + ((l >> 3) & 1) * 8;   // A: row-in-16
    const int acol_l = (l >> 4) & 1;                   // A: k-half chunk
    const int brow_l = (l & 7) + ((l >> 4) & 1) * 8;   // B: n-row-in-16
    const int bcol_l = (l >> 3) & 1;                   // B: k-half chunk

    int abase[4], asw[4];
    #pragma unroll
    for (int i = 0; i < 4; i++) {
        const int mrow = wm * 64 + i * 16 + arow_l;
        abase[i] = mrow * 128;
        asw[i]   = mrow & 7;
    }
    int bbase[4], bsw[4];
    #pragma unroll
    for (int jj = 0; jj < 4; jj++) {
        const int nrow = wn * 64 + jj * 16 + brow_l;
        bbase[jj] = nrow * 128;
        bsw[jj]   = nrow & 7;
    }

    // ks-stagger: warps sharing an SMSP (w and w+4) start at different ks
    const int ks0 = ((w >> 2) & 1) << 1;

    // Prologue: stages 0, 1
    stage_ld(smem,       smem + 16384,       Ag, lda, Bg, ldb, 0,  tid); cp_commit();
    stage_ld(smem + STG, smem + STG + 16384, Ag, lda, Bg, ldb, 64, tid); cp_commit();

    #pragma unroll 1
    for (int t = 0; t < T; t++) {
        cp_wait<1>();
        __syncthreads();
        if (t + 2 < T) {
            const int s2 = (t + 2) % 3;
            stage_ld(smem + s2 * STG, smem + s2 * STG + 16384,
                     Ag, lda, Bg, ldb, (t + 2) * 64, tid);
        }
        cp_commit();

        const uint32_t sA = smem + (t % 3) * STG;
        const uint32_t sB = sA + 16384;
        #pragma unroll
        for (int kss = 0; kss < 4; kss++) {
            const int ks = (kss + ks0) & 3;
            uint32_t af[4][4];
            #pragma unroll
            for (int i = 0; i < 4; i++)
                ldsm_x4(sA + abase[i] + (((ks * 2 + acol_l) ^ asw[i]) * 16),
                        af[i][0], af[i][1], af[i][2], af[i][3]);
            uint32_t bf[8][2];
            #pragma unroll
            for (int jj = 0; jj < 4; jj++)
                ldsm_x4(sB + bbase[jj] + (((ks * 2 + bcol_l) ^ bsw[jj]) * 16),
                        bf[jj * 2][0], bf[jj * 2][1], bf[jj * 2 + 1][0], bf[jj * 2 + 1][1]);
            #pragma unroll
            for (int i = 0; i < 4; i++)
                #pragma unroll
                for (int j = 0; j < 8; j++)
                    mma16816(acc[i][j], af[i], bf[j]);
        }
    }

    // Epilogue: lane l holds rows (l>>2) and (l>>2)+8, cols 2*(l&3)
    const int r4 = l >> 2;
    const int c2 = (l & 3) * 2;
    #pragma unroll
    for (int i = 0; i < 4; i++) {
        const int row_a = m0 + wm * 64 + i * 16 + r4;
        #pragma unroll
        for (int h = 0; h < 2; h++) {
            const int row = row_a + h * 8;
            #pragma unroll
            for (int j = 0; j < 8; j++) {
                const int col = n0 + wn * 64 + j * 8 + c2;
                if (EPI == 0) {
                    const __half2 hv = __floats2half2_rn(acc[i][j][h * 2],
                                                         acc[i][j][h * 2 + 1]);
                    *(__half2*)((__half*)C + (size_t)row * ldc + col) = hv;
                } else {
                    const float bv = bias[row];
                    const int bb = col / HW;
                    const int hw = col - bb * HW;
                    float2 v = make_float2(acc[i][j][h * 2] + bv,
                                           acc[i][j][h * 2 + 1] + bv);
                    *(float2*)((float*)C + ((size_t)bb * DIMC + row) * HW + hw) = v;
                }
            }
        }
    }
}

// ---------------- attention: warp per (pixel, 4-head quad) ----------------
// Lane owns 8 consecutive d of ONE head: 8-lane group per head, 2 head-quads/pixel.
// 16B tap loads; 3-stage butterfly within 8-lane groups.
struct H2x4 { __half2 h[4]; };   // 16-byte packed store

__device__ __forceinline__ void ld_h8(const __half* p, float2 f[4]) {
    const uint4 raw = *(const uint4*)p;
    f[0] = __half22float2(*(const __half2*)&raw.x);
    f[1] = __half22float2(*(const __half2*)&raw.y);
    f[2] = __half22float2(*(const __half2*)&raw.z);
    f[3] = __half22float2(*(const __half2*)&raw.w);
}
__device__ __forceinline__ float dot8(const float2 a[4], const float2 b[4]) {
    float d = a[0].x * b[0].x;
    d = fmaf(a[0].y, b[0].y, d);
    d = fmaf(a[1].x, b[1].x, d);
    d = fmaf(a[1].y, b[1].y, d);
    d = fmaf(a[2].x, b[2].x, d);
    d = fmaf(a[2].y, b[2].y, d);
    d = fmaf(a[3].x, b[3].x, d);
    d = fmaf(a[3].y, b[3].y, d);
    return d;
}

__global__ __launch_bounds__(256) void attn_kernel(
    const __half* __restrict__ qkvT, __half* __restrict__ aoT)
{
    const int w  = threadIdx.x >> 5;
    const int l  = threadIdx.x & 31;
    const int x  = blockIdx.x * 4 + (w >> 1);
    const int y  = blockIdx.y;
    const int b  = blockIdx.z;
    const int wq = w & 1;                          // head quad 0..1
    const int chb = wq * 256 + (l >> 3) * 64 + (l & 7) * 8;

    const __half* base = qkvT + (size_t)(b * HW + y * IMG_W + x) * QKV_CH;
    float2 q[4];
    ld_h8(base + chb, q);

    const bool interior = (x >= 1) && (x <= IMG_W - 2) && (y >= 1) && (y <= IMG_H - 2);

    float dots[9];
    if (interior) {
        #pragma unroll
        for (int r = 0; r < 3; r++) {
            const __half* krow = base + ((r - 1) * IMG_W - 1) * QKV_CH + INNER + chb;
            #pragma unroll
            for (int c = 0; c < 3; c++) {
                float2 kk[4];
                ld_h8(krow + c * QKV_CH, kk);
                dots[r * 3 + c] = dot8(q, kk);
            }
        }
    } else {
        #pragma unroll
        for (int t = 0; t < 9; t++) {
            const int yy = y + t / 3 - 1;
            const int xx = x + t % 3 - 1;
            float d = 0.f;
            if (yy >= 0 && yy < IMG_H && xx >= 0 && xx < IMG_W) {
                float2 kk[4];
                ld_h8(qkvT + (size_t)(b * HW + yy * IMG_W + xx) * QKV_CH + INNER + chb, kk);
                d = dot8(q, kk);
            }
            dots[t] = d;
        }
    }

    // 3-stage butterfly within each 8-lane (one-head) group
    #pragma unroll
    for (int off = 4; off; off >>= 1)
        #pragma unroll
        for (int t = 0; t < 9; t++)
            dots[t] += __shfl_xor_sync(0xFFFFFFFFu, dots[t], off);

    float m = -1e30f;
    #pragma unroll
    for (int t = 0; t < 9; t++) { dots[t] *= SCALE; m = fmaxf(m, dots[t]); }
    float wgt[9], s = 0.f;
    #pragma unroll
    for (int t = 0; t < 9; t++) { wgt[t] = __expf(dots[t] - m); s += wgt[t]; }
    const float inv = 1.f / s;
    #pragma unroll
    for (int t = 0; t < 9; t++) wgt[t] *= inv;

    float2 o[4];
    #pragma unroll
    for (int i = 0; i < 4; i++) o[i] = make_float2(0.f, 0.f);

    if (interior) {
        #pragma unroll
        for (int r = 0; r < 3; r++) {
            const __half* vrow = base + ((r - 1) * IMG_W - 1) * QKV_CH + 2 * INNER + chb;
            #pragma unroll
            for (int c = 0; c < 3; c++) {
                float2 vv[4];
                ld_h8(vrow + c * QKV_CH, vv);
                const float wt = wgt[r * 3 + c];
                #pragma unroll
                for (int i = 0; i < 4; i++) {
                    o[i].x = fmaf(wt, vv[i].x, o[i].x);
                    o[i].y = fmaf(wt, vv[i].y, o[i].y);
                }
            }
        }
    } else {
        #pragma unroll
        for (int t = 0; t < 9; t++) {
            const int yy = y + t / 3 - 1;
            const int xx = x + t % 3 - 1;
            if (yy >= 0 && yy < IMG_H && xx >= 0 && xx < IMG_W) {
                float2 vv[4];
                ld_h8(qkvT + (size_t)(b * HW + yy * IMG_W + xx) * QKV_CH + 2 * INNER + chb, vv);
                const float wt = wgt[t];
                #pragma unroll
                for (int i = 0; i < 4; i++) {
                    o[i].x = fmaf(wt, vv[i].x, o[i].x);
                    o[i].y = fmaf(wt, vv[i].y, o[i].y);
                }
            }
        }
    }

    H2x4 packed;
    packed.h[0] = __floats2half2_rn(o[0].x, o[0].y);
    packed.h[1] = __floats2half2_rn(o[1].x, o[1].y);
    packed.h[2] = __floats2half2_rn(o[2].x, o[2].y);
    packed.h[3] = __floats2half2_rn(o[3].x, o[3].y);
    *(H2x4*)(aoT + (size_t)(b * HW + y * IMG_W + x) * INNER + chb) = packed;
}

// ---------------- launch ----------------
extern "C" void kernel_launch(void* const* d_in, const int* in_sizes, int n_in,
                              void* d_out, int out_size)
{
    const float* x   = (const float*)d_in[0];
    const float* Wq  = (const float*)d_in[1];
    const float* Wkv = (const float*)d_in[2];
    const float* Wo  = (const float*)d_in[3];
    const float* bo  = (const float*)d_in[4];
    float* out = (float*)d_out;

    __half *xT, *wqkv, *wo, *qkvT, *aoT;
    cudaGetSymbolAddress((void**)&xT,   g_xT);
    cudaGetSymbolAddress((void**)&wqkv, g_wqkv);
    cudaGetSymbolAddress((void**)&wo,   g_wo);
    cudaGetSymbolAddress((void**)&qkvT, g_qkvT);
    cudaGetSymbolAddress((void**)&aoT,  g_aoT);

    const int gemm_smem = 3 * STG;   // 144 KB
    cudaFuncSetAttribute((const void*)hmma_gemm<K1 / 64, 0>,
                         cudaFuncAttributeMaxDynamicSharedMemorySize, gemm_smem);
    cudaFuncSetAttribute((const void*)hmma_gemm<K2 / 64, 1>,
                         cudaFuncAttributeMaxDynamicSharedMemorySize, gemm_smem);

    // 0) converts
    weights_convert<<<QKV_CH + DIMC, 512>>>(Wq, Wkv, Wo, wqkv, wo);
    transpose_convert<<<dim3(HW / 32, DIMC / 32, BATCH), dim3(32, 8)>>>(x, xT);

    // 1) qkv projection: D[p][ch] fp16, M=12544, N=1536, K=384
    hmma_gemm<K1 / 64, 0><<<dim3(QKV_CH / 256, NPIX / 128), 256, gemm_smem>>>(
        xT, K1, wqkv, DIMC, nullptr, qkvT, QKV_CH);

    // 2) neighborhood attention (warp per pixel-head-quad)
    attn_kernel<<<dim3(IMG_W / 4, IMG_H, BATCH), 256>>>(qkvT, aoT);

    // 3) out projection: D[ch][p] -> out (channel-major) + bias, K=512
    hmma_gemm<K2 / 64, 1><<<dim3(NPIX / 256, DIMC / 128), 256, gemm_smem>>>(
        wo, K2, aoT, INNER, bo, out, 0);
}

// round 14
// speedup vs baseline: 1.4237x; 1.4237x over previous
#include <cuda_runtime.h>
#include <cuda_fp16.h>
#include <cstdint>
#include <cstddef>

#define BATCH   4
#define DIMC    384
#define HEADS   8
#define DHEAD   64
#define INNER   512
#define QKV_CH  1536
#define IMG_H   56
#define IMG_W   56
#define HW      3136
#define NPIX    (BATCH * HW)      // 12544
#define SCALE   0.125f

#define K1      384               // GEMM1: plain fp16
#define K2      512               // GEMM2: plain fp16

// Scratch (device globals; allocation forbidden)
__device__ __half g_xT  [(size_t)NPIX * K1];      // A1: hi of x, pixel-major
__device__ __half g_wqkv[(size_t)QKV_CH * DIMC];  // B1: hi
__device__ __half g_wo  [(size_t)DIMC * K2];      // A2: hi of Wo
__device__ __half g_qkvT[(size_t)NPIX * QKV_CH];  // pixel-major q|k|v (fp16)
__device__ __half g_aoT [(size_t)NPIX * INNER];   // B2: hi

// ---------------- PTX helpers (baseline sm_80+ features only) ----------------
__device__ __forceinline__ uint32_t smem_u32(const void* p) {
    uint32_t a;
    asm("{ .reg .u64 t; cvta.to.shared.u64 t, %1; cvt.u32.u64 %0, t; }" : "=r"(a) : "l"(p));
    return a;
}
__device__ __forceinline__ void cp_async16(uint32_t saddr, const void* gptr) {
    asm volatile("cp.async.cg.shared.global [%0], [%1], 16;\n" :: "r"(saddr), "l"(gptr));
}
__device__ __forceinline__ void cp_commit() {
    asm volatile("cp.async.commit_group;\n" ::: "memory");
}
template <int N> __device__ __forceinline__ void cp_wait() {
    asm volatile("cp.async.wait_group %0;\n" :: "n"(N) : "memory");
}
__device__ __forceinline__ void ldsm_x4(uint32_t addr, uint32_t& r0, uint32_t& r1,
                                        uint32_t& r2, uint32_t& r3) {
    asm volatile("ldmatrix.sync.aligned.m8n8.x4.shared.b16 {%0,%1,%2,%3}, [%4];"
                 : "=r"(r0), "=r"(r1), "=r"(r2), "=r"(r3) : "r"(addr));
}
__device__ __forceinline__ void mma16816(float* d, const uint32_t* a, const uint32_t* b) {
    asm volatile("mma.sync.aligned.m16n8k16.row.col.f32.f16.f16.f32 "
        "{%0,%1,%2,%3}, {%4,%5,%6,%7}, {%8,%9}, {%0,%1,%2,%3};"
        : "+f"(d[0]), "+f"(d[1]), "+f"(d[2]), "+f"(d[3])
        : "r"(a[0]), "r"(a[1]), "r"(a[2]), "r"(a[3]), "r"(b[0]), "r"(b[1]));
}

// ---------------- input converts ----------------
__global__ __launch_bounds__(256) void transpose_convert(
    const float* __restrict__ x, __half* __restrict__ xT)
{
    __shared__ float t[32][33];
    const int p0 = blockIdx.x * 32, c0 = blockIdx.y * 32, b = blockIdx.z;
    const int tx = threadIdx.x, ty = threadIdx.y;
    const float* src = x + (size_t)b * DIMC * HW;
    #pragma unroll
    for (int i = 0; i < 32; i += 8)
        t[ty + i][tx] = src[(size_t)(c0 + ty + i) * HW + p0 + tx];
    __syncthreads();
    __half* dst = xT + (size_t)b * HW * K1;
    #pragma unroll
    for (int i = 0; i < 32; i += 8) {
        const size_t row = (size_t)(p0 + ty + i) * K1;
        dst[row + c0 + tx] = __float2half(t[tx][ty + i]);
    }
}

// Merged weight converts: blocks [0,1536) -> wqkv hi; [1536,1920) -> wo hi
__global__ __launch_bounds__(512) void weights_convert(
    const float* __restrict__ Wq, const float* __restrict__ Wkv,
    const float* __restrict__ Wo,
    __half* __restrict__ wqkv, __half* __restrict__ wo)
{
    const int blk = blockIdx.x;
    const int k = threadIdx.x;
    if (blk < QKV_CH) {
        if (k < DIMC) {
            const float w = (blk < INNER) ? Wq[(size_t)blk * DIMC + k]
                                          : Wkv[(size_t)(blk - INNER) * DIMC + k];
            wqkv[(size_t)blk * DIMC + k] = __float2half(w);
        }
    } else {
        const int row = blk - QKV_CH;
        wo[(size_t)row * K2 + k] = __float2half(Wo[(size_t)row * INNER + k]);
    }
}

// ---------------- mma.sync fp16 GEMM ----------------
// D[m][n] = sum_k A[m][k]*B[n][k]; CTA tile 128x256, K-chunk 64, 3-stage cp.async.
// 8 warps 2(M)x4(N), warp 64x64. EPI 0: C __half*, row-major ldc.
// EPI 1: C float*, channel-major + bias.
#define STG 49152   // per stage: A 128*128B (16KB) + B 256*128B (32KB)

__device__ __forceinline__ void stage_ld(uint32_t sA, uint32_t sB,
    const __half* __restrict__ Ag, int lda,
    const __half* __restrict__ Bg, int ldb, int kt, int tid)
{
    #pragma unroll
    for (int i = 0; i < 4; i++) {
        const int idx = tid + i * 256;
        const int row = idx >> 3, j = idx & 7;
        const uint32_t off = (uint32_t)(row * 128 + ((j ^ (row & 7)) * 16));
        cp_async16(sA + off, Ag + (size_t)row * lda + kt + j * 8);
    }
    #pragma unroll
    for (int i = 0; i < 8; i++) {
        const int idx = tid + i * 256;
        const int row = idx >> 3, j = idx & 7;
        const uint32_t off = (uint32_t)(row * 128 + ((j ^ (row & 7)) * 16));
        cp_async16(sB + off, Bg + (size_t)row * ldb + kt + j * 8);
    }
}

template <int T, int EPI>
__global__ __launch_bounds__(256) void hmma_gemm(
    const __half* __restrict__ A, int lda,
    const __half* __restrict__ B, int ldb,
    const float* __restrict__ bias, void* __restrict__ C, int ldc)
{
    extern __shared__ char dynraw[];
    const uint32_t smem = smem_u32(dynraw);
    const int tid = threadIdx.x;
    const int w = tid >> 5, l = tid & 31;
    const int wm = w >> 2, wn = w & 3;
    const int n0 = blockIdx.x * 256, m0 = blockIdx.y * 128;

    const __half* Ag = A + (size_t)m0 * lda;
    const __half* Bg = B + (size_t)n0 * ldb;

    float acc[4][8][4];
    #pragma unroll
    for (int i = 0; i < 4; i++)
        #pragma unroll
        for (int j = 0; j < 8; j++)
            #pragma unroll
            for (int c = 0; c < 4; c++) acc[i][j][c] = 0.f;

    // ldmatrix lane constants (all non-trans; K-major operands)
    const int arow_l = (l & 7) + ((l >> 3) & 1) * 8;   // A: row-in-16
    const int acol_l = (l >> 4) & 1;                   // A: k-half chunk
    const int brow_l = (l & 7) + ((l >> 4) & 1) * 8;   // B: n-row-in-16
    const int bcol_l = (l >> 3) & 1;                   // B: k-half chunk

    int abase[4], asw[4];
    #pragma unroll
    for (int i = 0; i < 4; i++) {
        const int mrow = wm * 64 + i * 16 + arow_l;
        abase[i] = mrow * 128;
        asw[i]   = mrow & 7;
    }
    int bbase[4], bsw[4];
    #pragma unroll
    for (int jj = 0; jj < 4; jj++) {
        const int nrow = wn * 64 + jj * 16 + brow_l;
        bbase[jj] = nrow * 128;
        bsw[jj]   = nrow & 7;
    }

    // ks-stagger: warps sharing an SMSP (w and w+4) start at different ks
    const int ks0 = ((w >> 2) & 1) << 1;

    // Prologue: stages 0, 1
    stage_ld(smem,       smem + 16384,       Ag, lda, Bg, ldb, 0,  tid); cp_commit();
    stage_ld(smem + STG, smem + STG + 16384, Ag, lda, Bg, ldb, 64, tid); cp_commit();

    #pragma unroll 1
    for (int t = 0; t < T; t++) {
        cp_wait<1>();
        __syncthreads();
        if (t + 2 < T) {
            const int s2 = (t + 2) % 3;
            stage_ld(smem + s2 * STG, smem + s2 * STG + 16384,
                     Ag, lda, Bg, ldb, (t + 2) * 64, tid);
        }
        cp_commit();

        const uint32_t sA = smem + (t % 3) * STG;
        const uint32_t sB = sA + 16384;
        #pragma unroll
        for (int kss = 0; kss < 4; kss++) {
            const int ks = (kss + ks0) & 3;
            uint32_t af[4][4];
            #pragma unroll
            for (int i = 0; i < 4; i++)
                ldsm_x4(sA + abase[i] + (((ks * 2 + acol_l) ^ asw[i]) * 16),
                        af[i][0], af[i][1], af[i][2], af[i][3]);
            uint32_t bf[8][2];
            #pragma unroll
            for (int jj = 0; jj < 4; jj++)
                ldsm_x4(sB + bbase[jj] + (((ks * 2 + bcol_l) ^ bsw[jj]) * 16),
                        bf[jj * 2][0], bf[jj * 2][1], bf[jj * 2 + 1][0], bf[jj * 2 + 1][1]);
            #pragma unroll
            for (int i = 0; i < 4; i++)
                #pragma unroll
                for (int j = 0; j < 8; j++)
                    mma16816(acc[i][j], af[i], bf[j]);
        }
    }

    // Epilogue: lane l holds rows (l>>2) and (l>>2)+8, cols 2*(l&3)
    const int r4 = l >> 2;
    const int c2 = (l & 3) * 2;
    #pragma unroll
    for (int i = 0; i < 4; i++) {
        const int row_a = m0 + wm * 64 + i * 16 + r4;
        #pragma unroll
        for (int h = 0; h < 2; h++) {
            const int row = row_a + h * 8;
            #pragma unroll
            for (int j = 0; j < 8; j++) {
                const int col = n0 + wn * 64 + j * 8 + c2;
                if (EPI == 0) {
                    const __half2 hv = __floats2half2_rn(acc[i][j][h * 2],
                                                         acc[i][j][h * 2 + 1]);
                    *(__half2*)((__half*)C + (size_t)row * ldc + col) = hv;
                } else {
                    const float bv = bias[row];
                    const int bb = col / HW;
                    const int hw = col - bb * HW;
                    float2 v = make_float2(acc[i][j][h * 2] + bv,
                                           acc[i][j][h * 2 + 1] + bv);
                    *(float2*)((float*)C + ((size_t)bb * DIMC + row) * HW + hw) = v;
                }
            }
        }
    }
}

// ---------------- attention: warp per (pixel, head-pair), fp16 qkv ----------------
// (R11 version — proven 24.6us / 32 regs / 86% occ)
// Lane owns 4 consecutive d of ONE head: lanes 0-15 -> head 2*hp, 16-31 -> 2*hp+1.
__device__ __forceinline__ float4 ld_h4(const __half* p) {
    const uint2 raw = *(const uint2*)p;
    const float2 a = __half22float2(*(const __half2*)&raw.x);
    const float2 b = __half22float2(*(const __half2*)&raw.y);
    return make_float4(a.x, a.y, b.x, b.y);
}

__global__ __launch_bounds__(256) void attn_kernel(
    const __half* __restrict__ qkvT, __half* __restrict__ aoT)
{
    const int w  = threadIdx.x >> 5;
    const int l  = threadIdx.x & 31;
    const int x  = blockIdx.x * 2 + (w >> 2);
    const int y  = blockIdx.y;
    const int b  = blockIdx.z;
    const int hp = w & 3;                  // head pair 0..3
    const int chb = hp * 128 + l * 4;      // offset within 512-channel block

    const __half* base = qkvT + (size_t)(b * HW + y * IMG_W + x) * QKV_CH;
    const float4 q = ld_h4(base + chb);

    const bool interior = (x >= 1) && (x <= IMG_W - 2) && (y >= 1) && (y <= IMG_H - 2);

    float dots[9];
    if (interior) {
        #pragma unroll
        for (int r = 0; r < 3; r++) {
            const __half* krow = base + ((r - 1) * IMG_W - 1) * QKV_CH + INNER + chb;
            #pragma unroll
            for (int c = 0; c < 3; c++) {
                const float4 kk = ld_h4(krow + c * QKV_CH);
                dots[r * 3 + c] = fmaf(q.x, kk.x,
                                  fmaf(q.y, kk.y,
                                  fmaf(q.z, kk.z, q.w * kk.w)));
            }
        }
    } else {
        #pragma unroll
        for (int t = 0; t < 9; t++) {
            const int yy = y + t / 3 - 1;
            const int xx = x + t % 3 - 1;
            float d = 0.f;
            if (yy >= 0 && yy < IMG_H && xx >= 0 && xx < IMG_W) {
                const float4 kk = ld_h4(
                    qkvT + (size_t)(b * HW + yy * IMG_W + xx) * QKV_CH + INNER + chb);
                d = fmaf(q.x, kk.x, fmaf(q.y, kk.y, fmaf(q.z, kk.z, q.w * kk.w)));
            }
            dots[t] = d;
        }
    }

    // 4-stage butterfly within each 16-lane (one-head) group
    #pragma unroll
    for (int off = 8; off; off >>= 1)
        #pragma unroll
        for (int t = 0; t < 9; t++)
            dots[t] += __shfl_xor_sync(0xFFFFFFFFu, dots[t], off);

    float m = -1e30f;
    #pragma unroll
    for (int t = 0; t < 9; t++) { dots[t] *= SCALE; m = fmaxf(m, dots[t]); }
    float wgt[9], s = 0.f;
    #pragma unroll
    for (int t = 0; t < 9; t++) { wgt[t] = __expf(dots[t] - m); s += wgt[t]; }
    const float inv = 1.f / s;
    #pragma unroll
    for (int t = 0; t < 9; t++) wgt[t] *= inv;

    float4 o = make_float4(0.f, 0.f, 0.f, 0.f);
    if (interior) {
        #pragma unroll
        for (int r = 0; r < 3; r++) {
            const __half* vrow = base + ((r - 1) * IMG_W - 1) * QKV_CH + 2 * INNER + chb;
            #pragma unroll
            for (int c = 0; c < 3; c++) {
                const float4 vv = ld_h4(vrow + c * QKV_CH);
                const float wt = wgt[r * 3 + c];
                o.x = fmaf(wt, vv.x, o.x);
                o.y = fmaf(wt, vv.y, o.y);
                o.z = fmaf(wt, vv.z, o.z);
                o.w = fmaf(wt, vv.w, o.w);
            }
        }
    } else {
        #pragma unroll
        for (int t = 0; t < 9; t++) {
            const int yy = y + t / 3 - 1;
            const int xx = x + t % 3 - 1;
            if (yy >= 0 && yy < IMG_H && xx >= 0 && xx < IMG_W) {
                const float4 vv = ld_h4(
                    qkvT + (size_t)(b * HW + yy * IMG_W + xx) * QKV_CH + 2 * INNER + chb);
                const float wt = wgt[t];
                o.x = fmaf(wt, vv.x, o.x);
                o.y = fmaf(wt, vv.y, o.y);
                o.z = fmaf(wt, vv.z, o.z);
                o.w = fmaf(wt, vv.w, o.w);
            }
        }
    }

    __half2 p0 = __floats2half2_rn(o.x, o.y);
    __half2 p1 = __floats2half2_rn(o.z, o.w);
    __half2* dst = (__half2*)(aoT + (size_t)(b * HW + y * IMG_W + x) * INNER + chb);
    dst[0] = p0;
    dst[1] = p1;
}

// ---------------- launch ----------------
extern "C" void kernel_launch(void* const* d_in, const int* in_sizes, int n_in,
                              void* d_out, int out_size)
{
    const float* x   = (const float*)d_in[0];
    const float* Wq  = (const float*)d_in[1];
    const float* Wkv = (const float*)d_in[2];
    const float* Wo  = (const float*)d_in[3];
    const float* bo  = (const float*)d_in[4];
    float* out = (float*)d_out;

    __half *xT, *wqkv, *wo, *qkvT, *aoT;
    cudaGetSymbolAddress((void**)&xT,   g_xT);
    cudaGetSymbolAddress((void**)&wqkv, g_wqkv);
    cudaGetSymbolAddress((void**)&wo,   g_wo);
    cudaGetSymbolAddress((void**)&qkvT, g_qkvT);
    cudaGetSymbolAddress((void**)&aoT,  g_aoT);

    const int gemm_smem = 3 * STG;   // 144 KB
    cudaFuncSetAttribute((const void*)hmma_gemm<K1 / 64, 0>,
                         cudaFuncAttributeMaxDynamicSharedMemorySize, gemm_smem);
    cudaFuncSetAttribute((const void*)hmma_gemm<K2 / 64, 1>,
                         cudaFuncAttributeMaxDynamicSharedMemorySize, gemm_smem);

    // 0) converts
    weights_convert<<<QKV_CH + DIMC, 512>>>(Wq, Wkv, Wo, wqkv, wo);
    transpose_convert<<<dim3(HW / 32, DIMC / 32, BATCH), dim3(32, 8)>>>(x, xT);

    // 1) qkv projection: D[p][ch] fp16, M=12544, N=1536, K=384
    hmma_gemm<K1 / 64, 0><<<dim3(QKV_CH / 256, NPIX / 128), 256, gemm_smem>>>(
        xT, K1, wqkv, DIMC, nullptr, qkvT, QKV_CH);

    // 2) neighborhood attention (warp per pixel-head-pair, fp16 qkv)
    attn_kernel<<<dim3(IMG_W / 2, IMG_H, BATCH), 256>>>(qkvT, aoT);

    // 3) out projection: D[ch][p] -> out (channel-major) + bias, K=512
    hmma_gemm<K2 / 64, 1><<<dim3(NPIX / 256, DIMC / 128), 256, gemm_smem>>>(
        wo, K2, aoT, INNER, bo, out, 0);
}

// round 15
// speedup vs baseline: 1.4588x; 1.0247x over previous
#include <cuda_runtime.h>
#include <cuda_fp16.h>
#include <cstdint>
#include <cstddef>

#define BATCH   4
#define DIMC    384
#define HEADS   8
#define DHEAD   64
#define INNER   512
#define QKV_CH  1536
#define IMG_H   56
#define IMG_W   56
#define HW      3136
#define NPIX    (BATCH * HW)      // 12544
#define SCALE   0.125f

#define K1      384               // GEMM1: plain fp16, A fused from fp32 x
#define K2      512               // GEMM2: plain fp16

// Scratch (device globals; allocation forbidden)
__device__ __half g_wqkv[(size_t)QKV_CH * DIMC];  // B1: hi
__device__ __half g_wo  [(size_t)DIMC * K2];      // A2: hi of Wo
__device__ __half g_qkvT[(size_t)NPIX * QKV_CH];  // pixel-major q|k|v (fp16)
__device__ __half g_aoT [(size_t)NPIX * INNER];   // B2: hi

// ---------------- PTX helpers (baseline sm_80+ features only) ----------------
__device__ __forceinline__ uint32_t smem_u32(const void* p) {
    uint32_t a;
    asm("{ .reg .u64 t; cvta.to.shared.u64 t, %1; cvt.u32.u64 %0, t; }" : "=r"(a) : "l"(p));
    return a;
}
__device__ __forceinline__ void cp_async16(uint32_t saddr, const void* gptr) {
    asm volatile("cp.async.cg.shared.global [%0], [%1], 16;\n" :: "r"(saddr), "l"(gptr));
}
__device__ __forceinline__ void cp_commit() {
    asm volatile("cp.async.commit_group;\n" ::: "memory");
}
template <int N> __device__ __forceinline__ void cp_wait() {
    asm volatile("cp.async.wait_group %0;\n" :: "n"(N) : "memory");
}
__device__ __forceinline__ void ldsm_x4(uint32_t addr, uint32_t& r0, uint32_t& r1,
                                        uint32_t& r2, uint32_t& r3) {
    asm volatile("ldmatrix.sync.aligned.m8n8.x4.shared.b16 {%0,%1,%2,%3}, [%4];"
                 : "=r"(r0), "=r"(r1), "=r"(r2), "=r"(r3) : "r"(addr));
}
__device__ __forceinline__ void ldsm_x4_t(uint32_t addr, uint32_t& r0, uint32_t& r1,
                                          uint32_t& r2, uint32_t& r3) {
    asm volatile("ldmatrix.sync.aligned.m8n8.x4.trans.shared.b16 {%0,%1,%2,%3}, [%4];"
                 : "=r"(r0), "=r"(r1), "=r"(r2), "=r"(r3) : "r"(addr));
}
__device__ __forceinline__ void mma16816(float* d, const uint32_t* a, const uint32_t* b) {
    asm volatile("mma.sync.aligned.m16n8k16.row.col.f32.f16.f16.f32 "
        "{%0,%1,%2,%3}, {%4,%5,%6,%7}, {%8,%9}, {%0,%1,%2,%3};"
        : "+f"(d[0]), "+f"(d[1]), "+f"(d[2]), "+f"(d[3])
        : "r"(a[0]), "r"(a[1]), "r"(a[2]), "r"(a[3]), "r"(b[0]), "r"(b[1]));
}
__device__ __forceinline__ void sts64(uint32_t addr, uint32_t u0, uint32_t u1) {
    asm volatile("st.shared.v2.u32 [%0], {%1,%2};" :: "r"(addr), "r"(u0), "r"(u1));
}

// ---------------- weight converts ----------------
__global__ __launch_bounds__(512) void weights_convert(
    const float* __restrict__ Wq, const float* __restrict__ Wkv,
    const float* __restrict__ Wo,
    __half* __restrict__ wqkv, __half* __restrict__ wo)
{
    const int blk = blockIdx.x;
    const int k = threadIdx.x;
    if (blk < QKV_CH) {
        if (k < DIMC) {
            const float w = (blk < INNER) ? Wq[(size_t)blk * DIMC + k]
                                          : Wkv[(size_t)(blk - INNER) * DIMC + k];
            wqkv[(size_t)blk * DIMC + k] = __float2half(w);
        }
    } else {
        const int row = blk - QKV_CH;
        wo[(size_t)row * K2 + k] = __float2half(Wo[(size_t)row * INNER + k]);
    }
}

// ---------------- GEMM1: fused transpose+convert A (x fp32), B cp.async ----------------
// D[m=pixel][n=ch] = sum_k x[ch? no: x[b][k][hw]] * wqkv[n][k]
// A smem: [k][px] fp16, 64 rows x 256B, swizzle chunk^= (k&7); frags via ldsm.trans.
// B smem: [n][k] fp16, 256 rows x 128B (as before).
#define BSTG 32768
#define ASTG 16384

__device__ __forceinline__ void b_stage_ld(uint32_t sB,
    const __half* __restrict__ Bg, int ldb, int kt, int tid)
{
    #pragma unroll
    for (int i = 0; i < 8; i++) {
        const int idx = tid + i * 256;
        const int row = idx >> 3, j = idx & 7;
        const uint32_t off = (uint32_t)(row * 128 + ((j ^ (row & 7)) * 16));
        cp_async16(sB + off, Bg + (size_t)row * ldb + kt + j * 8);
    }
}

__device__ __forceinline__ void a_ldg(float4 pf[4], const float* __restrict__ xbase,
    const float* __restrict__ X, int m0, int kt, int tid, int half, bool straddle)
{
    #pragma unroll
    for (int i = 0; i < 4; i++) {
        const int idx = tid + (half * 4 + i) * 256;
        const int c = idx >> 5, pxg = idx & 31;
        if (!straddle) {
            pf[i] = *(const float4*)(xbase + (size_t)(kt + c) * HW + pxg * 4);
        } else {
            float t[4];
            #pragma unroll
            for (int j = 0; j < 4; j++) {
                const int pg = m0 + pxg * 4 + j;
                const int bb = pg / HW;
                const int hw = pg - bb * HW;
                t[j] = X[(size_t)bb * DIMC * HW + (size_t)(kt + c) * HW + hw];
            }
            pf[i] = make_float4(t[0], t[1], t[2], t[3]);
        }
    }
}

__device__ __forceinline__ void a_sts(uint32_t sA, const float4 pf[4], int tid, int half)
{
    #pragma unroll
    for (int i = 0; i < 4; i++) {
        const int idx = tid + (half * 4 + i) * 256;
        const int c = idx >> 5, pxg = idx & 31;
        const uint32_t addr = sA + c * 256 +
            ((((pxg >> 1) ^ (c & 7)) << 4) | ((pxg & 1) << 3));
        const __half2 h0 = __floats2half2_rn(pf[i].x, pf[i].y);
        const __half2 h1 = __floats2half2_rn(pf[i].z, pf[i].w);
        sts64(addr, *(const uint32_t*)&h0, *(const uint32_t*)&h1);
    }
}

template <int T>
__global__ __launch_bounds__(256) void hmma_gemm_xa(
    const float* __restrict__ X,
    const __half* __restrict__ B, int ldb,
    __half* __restrict__ C, int ldc)
{
    extern __shared__ char dynraw[];
    const uint32_t smem = smem_u32(dynraw);
    const uint32_t sBst = smem;                 // 3 x 32KB
    const uint32_t sAbuf = smem + 3 * BSTG;     // 2 x 16KB
    const int tid = threadIdx.x;
    const int w = tid >> 5, l = tid & 31;
    const int wm = w >> 2, wn = w & 3;
    const int n0 = blockIdx.x * 256, m0 = blockIdx.y * 128;

    const int b0 = m0 / HW;
    const bool straddle = ((m0 + 127) / HW) != b0;
    const float* xbase = X + (size_t)b0 * DIMC * HW + (m0 - b0 * HW);
    const __half* Bg = B + (size_t)n0 * ldb;

    float acc[4][8][4];
    #pragma unroll
    for (int i = 0; i < 4; i++)
        #pragma unroll
        for (int j = 0; j < 8; j++)
            #pragma unroll
            for (int c = 0; c < 4; c++) acc[i][j][c] = 0.f;

    // A (trans) lane constants: tile r <- AT[kbase + lane%8][mbase]
    const int krow_l = (l & 7) + ((l >> 4) & 1) * 8;   // k row within 16
    const int mch_l  = ((l >> 3) & 1) * 8;             // m col 0 or 8
    const int arowb  = krow_l * 256;
    int amoff[4];
    #pragma unroll
    for (int mi = 0; mi < 4; mi++) {
        const int m_off = wm * 64 + mi * 16 + mch_l;
        amoff[mi] = (((m_off >> 3) ^ (l & 7)) << 4);
    }
    // B lane constants (non-trans, K-major)
    const int brow_l = (l & 7) + ((l >> 4) & 1) * 8;
    const int bcol_l = (l >> 3) & 1;
    int bbase[4], bsw[4];
    #pragma unroll
    for (int jj = 0; jj < 4; jj++) {
        const int nrow = wn * 64 + jj * 16 + brow_l;
        bbase[jj] = nrow * 128;
        bsw[jj]   = nrow & 7;
    }

    // Prologue: B(0), B(1) async; A(0) synchronous produce
    b_stage_ld(sBst,        Bg, ldb, 0,  tid); cp_commit();
    b_stage_ld(sBst + BSTG, Bg, ldb, 64, tid); cp_commit();
    {
        float4 pf[4];
        a_ldg(pf, xbase, X, m0, 0, tid, 0, straddle);
        a_sts(sAbuf, pf, tid, 0);
        a_ldg(pf, xbase, X, m0, 0, tid, 1, straddle);
        a_sts(sAbuf, pf, tid, 1);
    }

    #pragma unroll 1
    for (int t = 0; t < T; t++) {
        cp_wait<1>();
        __syncthreads();

        float4 pf[4];
        const bool prodA = (t + 1 < T);
        if (prodA) a_ldg(pf, xbase, X, m0, (t + 1) * 64, tid, 0, straddle);
        if (t + 2 < T) b_stage_ld(sBst + ((t + 2) % 3) * BSTG, Bg, ldb, (t + 2) * 64, tid);
        cp_commit();

        const uint32_t sA = sAbuf + (t & 1) * ASTG;
        const uint32_t sAn = sAbuf + ((t + 1) & 1) * ASTG;
        const uint32_t sB = sBst + (t % 3) * BSTG;

        #pragma unroll
        for (int ks = 0; ks < 4; ks++) {
            uint32_t af[4][4];
            #pragma unroll
            for (int mi = 0; mi < 4; mi++)
                ldsm_x4_t(sA + arowb + ks * 4096 + amoff[mi],
                          af[mi][0], af[mi][1], af[mi][2], af[mi][3]);
            uint32_t bf[8][2];
            #pragma unroll
            for (int jj = 0; jj < 4; jj++)
                ldsm_x4(sB + bbase[jj] + (((ks * 2 + bcol_l) ^ bsw[jj]) * 16),
                        bf[jj * 2][0], bf[jj * 2][1], bf[jj * 2 + 1][0], bf[jj * 2 + 1][1]);
            #pragma unroll
            for (int i = 0; i < 4; i++)
                #pragma unroll
                for (int j = 0; j < 8; j++)
                    mma16816(acc[i][j], af[i], bf[j]);
            if (ks == 1 && prodA) {
                a_sts(sAn, pf, tid, 0);
                a_ldg(pf, xbase, X, m0, (t + 1) * 64, tid, 1, straddle);
            }
        }
        if (prodA) a_sts(sAn, pf, tid, 1);
    }

    // Epilogue: lane l holds rows (l>>2) and (l>>2)+8, cols 2*(l&3); fp16 out
    const int r4 = l >> 2;
    const int c2 = (l & 3) * 2;
    #pragma unroll
    for (int i = 0; i < 4; i++) {
        const int row_a = m0 + wm * 64 + i * 16 + r4;
        #pragma unroll
        for (int h = 0; h < 2; h++) {
            const int row = row_a + h * 8;
            #pragma unroll
            for (int j = 0; j < 8; j++) {
                const int col = n0 + wn * 64 + j * 8 + c2;
                const __half2 hv = __floats2half2_rn(acc[i][j][h * 2],
                                                     acc[i][j][h * 2 + 1]);
                *(__half2*)(C + (size_t)row * ldc + col) = hv;
            }
        }
    }
}

// ---------------- GEMM2: plain fp16 both sides (as R14) ----------------
#define STG 49152

__device__ __forceinline__ void stage_ld(uint32_t sA, uint32_t sB,
    const __half* __restrict__ Ag, int lda,
    const __half* __restrict__ Bg, int ldb, int kt, int tid)
{
    #pragma unroll
    for (int i = 0; i < 4; i++) {
        const int idx = tid + i * 256;
        const int row = idx >> 3, j = idx & 7;
        const uint32_t off = (uint32_t)(row * 128 + ((j ^ (row & 7)) * 16));
        cp_async16(sA + off, Ag + (size_t)row * lda + kt + j * 8);
    }
    #pragma unroll
    for (int i = 0; i < 8; i++) {
        const int idx = tid + i * 256;
        const int row = idx >> 3, j = idx & 7;
        const uint32_t off = (uint32_t)(row * 128 + ((j ^ (row & 7)) * 16));
        cp_async16(sB + off, Bg + (size_t)row * ldb + kt + j * 8);
    }
}

template <int T>
__global__ __launch_bounds__(256) void hmma_gemm(
    const __half* __restrict__ A, int lda,
    const __half* __restrict__ B, int ldb,
    const float* __restrict__ bias, float* __restrict__ C)
{
    extern __shared__ char dynraw[];
    const uint32_t smem = smem_u32(dynraw);
    const int tid = threadIdx.x;
    const int w = tid >> 5, l = tid & 31;
    const int wm = w >> 2, wn = w & 3;
    const int n0 = blockIdx.x * 256, m0 = blockIdx.y * 128;

    const __half* Ag = A + (size_t)m0 * lda;
    const __half* Bg = B + (size_t)n0 * ldb;

    float acc[4][8][4];
    #pragma unroll
    for (int i = 0; i < 4; i++)
        #pragma unroll
        for (int j = 0; j < 8; j++)
            #pragma unroll
            for (int c = 0; c < 4; c++) acc[i][j][c] = 0.f;

    const int arow_l = (l & 7) + ((l >> 3) & 1) * 8;
    const int acol_l = (l >> 4) & 1;
    const int brow_l = (l & 7) + ((l >> 4) & 1) * 8;
    const int bcol_l = (l >> 3) & 1;

    int abase[4], asw[4];
    #pragma unroll
    for (int i = 0; i < 4; i++) {
        const int mrow = wm * 64 + i * 16 + arow_l;
        abase[i] = mrow * 128;
        asw[i]   = mrow & 7;
    }
    int bbase[4], bsw[4];
    #pragma unroll
    for (int jj = 0; jj < 4; jj++) {
        const int nrow = wn * 64 + jj * 16 + brow_l;
        bbase[jj] = nrow * 128;
        bsw[jj]   = nrow & 7;
    }

    const int ks0 = ((w >> 2) & 1) << 1;

    stage_ld(smem,       smem + 16384,       Ag, lda, Bg, ldb, 0,  tid); cp_commit();
    stage_ld(smem + STG, smem + STG + 16384, Ag, lda, Bg, ldb, 64, tid); cp_commit();

    #pragma unroll 1
    for (int t = 0; t < T; t++) {
        cp_wait<1>();
        __syncthreads();
        if (t + 2 < T) {
            const int s2 = (t + 2) % 3;
            stage_ld(smem + s2 * STG, smem + s2 * STG + 16384,
                     Ag, lda, Bg, ldb, (t + 2) * 64, tid);
        }
        cp_commit();

        const uint32_t sA = smem + (t % 3) * STG;
        const uint32_t sB = sA + 16384;
        #pragma unroll
        for (int kss = 0; kss < 4; kss++) {
            const int ks = (kss + ks0) & 3;
            uint32_t af[4][4];
            #pragma unroll
            for (int i = 0; i < 4; i++)
                ldsm_x4(sA + abase[i] + (((ks * 2 + acol_l) ^ asw[i]) * 16),
                        af[i][0], af[i][1], af[i][2], af[i][3]);
            uint32_t bf[8][2];
            #pragma unroll
            for (int jj = 0; jj < 4; jj++)
                ldsm_x4(sB + bbase[jj] + (((ks * 2 + bcol_l) ^ bsw[jj]) * 16),
                        bf[jj * 2][0], bf[jj * 2][1], bf[jj * 2 + 1][0], bf[jj * 2 + 1][1]);
            #pragma unroll
            for (int i = 0; i < 4; i++)
                #pragma unroll
                for (int j = 0; j < 8; j++)
                    mma16816(acc[i][j], af[i], bf[j]);
        }
    }

    const int r4 = l >> 2;
    const int c2 = (l & 3) * 2;
    #pragma unroll
    for (int i = 0; i < 4; i++) {
        const int row_a = m0 + wm * 64 + i * 16 + r4;
        #pragma unroll
        for (int h = 0; h < 2; h++) {
            const int row = row_a + h * 8;
            const float bv = bias[row];
            #pragma unroll
            for (int j = 0; j < 8; j++) {
                const int col = n0 + wn * 64 + j * 8 + c2;
                const int bb = col / HW;
                const int hw = col - bb * HW;
                float2 v = make_float2(acc[i][j][h * 2] + bv,
                                       acc[i][j][h * 2 + 1] + bv);
                *(float2*)(C + ((size_t)bb * DIMC + row) * HW + hw) = v;
            }
        }
    }
}

// ---------------- attention: warp per (pixel, head-pair), fp16 qkv (R11) ----------------
__device__ __forceinline__ float4 ld_h4(const __half* p) {
    const uint2 raw = *(const uint2*)p;
    const float2 a = __half22float2(*(const __half2*)&raw.x);
    const float2 b = __half22float2(*(const __half2*)&raw.y);
    return make_float4(a.x, a.y, b.x, b.y);
}

__global__ __launch_bounds__(256) void attn_kernel(
    const __half* __restrict__ qkvT, __half* __restrict__ aoT)
{
    const int w  = threadIdx.x >> 5;
    const int l  = threadIdx.x & 31;
    const int x  = blockIdx.x * 2 + (w >> 2);
    const int y  = blockIdx.y;
    const int b  = blockIdx.z;
    const int hp = w & 3;
    const int chb = hp * 128 + l * 4;

    const __half* base = qkvT + (size_t)(b * HW + y * IMG_W + x) * QKV_CH;
    const float4 q = ld_h4(base + chb);

    const bool interior = (x >= 1) && (x <= IMG_W - 2) && (y >= 1) && (y <= IMG_H - 2);

    float dots[9];
    if (interior) {
        #pragma unroll
        for (int r = 0; r < 3; r++) {
            const __half* krow = base + ((r - 1) * IMG_W - 1) * QKV_CH + INNER + chb;
            #pragma unroll
            for (int c = 0; c < 3; c++) {
                const float4 kk = ld_h4(krow + c * QKV_CH);
                dots[r * 3 + c] = fmaf(q.x, kk.x,
                                  fmaf(q.y, kk.y,
                                  fmaf(q.z, kk.z, q.w * kk.w)));
            }
        }
    } else {
        #pragma unroll
        for (int t = 0; t < 9; t++) {
            const int yy = y + t / 3 - 1;
            const int xx = x + t % 3 - 1;
            float d = 0.f;
            if (yy >= 0 && yy < IMG_H && xx >= 0 && xx < IMG_W) {
                const float4 kk = ld_h4(
                    qkvT + (size_t)(b * HW + yy * IMG_W + xx) * QKV_CH + INNER + chb);
                d = fmaf(q.x, kk.x, fmaf(q.y, kk.y, fmaf(q.z, kk.z, q.w * kk.w)));
            }
            dots[t] = d;
        }
    }

    #pragma unroll
    for (int off = 8; off; off >>= 1)
        #pragma unroll
        for (int t = 0; t < 9; t++)
            dots[t] += __shfl_xor_sync(0xFFFFFFFFu, dots[t], off);

    float m = -1e30f;
    #pragma unroll
    for (int t = 0; t < 9; t++) { dots[t] *= SCALE; m = fmaxf(m, dots[t]); }
    float wgt[9], s = 0.f;
    #pragma unroll
    for (int t = 0; t < 9; t++) { wgt[t] = __expf(dots[t] - m); s += wgt[t]; }
    const float inv = 1.f / s;
    #pragma unroll
    for (int t = 0; t < 9; t++) wgt[t] *= inv;

    float4 o = make_float4(0.f, 0.f, 0.f, 0.f);
    if (interior) {
        #pragma unroll
        for (int r = 0; r < 3; r++) {
            const __half* vrow = base + ((r - 1) * IMG_W - 1) * QKV_CH + 2 * INNER + chb;
            #pragma unroll
            for (int c = 0; c < 3; c++) {
                const float4 vv = ld_h4(vrow + c * QKV_CH);
                const float wt = wgt[r * 3 + c];
                o.x = fmaf(wt, vv.x, o.x);
                o.y = fmaf(wt, vv.y, o.y);
                o.z = fmaf(wt, vv.z, o.z);
                o.w = fmaf(wt, vv.w, o.w);
            }
        }
    } else {
        #pragma unroll
        for (int t = 0; t < 9; t++) {
            const int yy = y + t / 3 - 1;
            const int xx = x + t % 3 - 1;
            if (yy >= 0 && yy < IMG_H && xx >= 0 && xx < IMG_W) {
                const float4 vv = ld_h4(
                    qkvT + (size_t)(b * HW + yy * IMG_W + xx) * QKV_CH + 2 * INNER + chb);
                const float wt = wgt[t];
                o.x = fmaf(wt, vv.x, o.x);
                o.y = fmaf(wt, vv.y, o.y);
                o.z = fmaf(wt, vv.z, o.z);
                o.w = fmaf(wt, vv.w, o.w);
            }
        }
    }

    __half2 p0 = __floats2half2_rn(o.x, o.y);
    __half2 p1 = __floats2half2_rn(o.z, o.w);
    __half2* dst = (__half2*)(aoT + (size_t)(b * HW + y * IMG_W + x) * INNER + chb);
    dst[0] = p0;
    dst[1] = p1;
}

// ---------------- launch ----------------
extern "C" void kernel_launch(void* const* d_in, const int* in_sizes, int n_in,
                              void* d_out, int out_size)
{
    const float* x   = (const float*)d_in[0];
    const float* Wq  = (const float*)d_in[1];
    const float* Wkv = (const float*)d_in[2];
    const float* Wo  = (const float*)d_in[3];
    const float* bo  = (const float*)d_in[4];
    float* out = (float*)d_out;

    __half *wqkv, *wo, *qkvT, *aoT;
    cudaGetSymbolAddress((void**)&wqkv, g_wqkv);
    cudaGetSymbolAddress((void**)&wo,   g_wo);
    cudaGetSymbolAddress((void**)&qkvT, g_qkvT);
    cudaGetSymbolAddress((void**)&aoT,  g_aoT);

    const int g1_smem = 3 * BSTG + 2 * ASTG;   // 128 KB
    const int g2_smem = 3 * STG;               // 144 KB
    cudaFuncSetAttribute((const void*)hmma_gemm_xa<K1 / 64>,
                         cudaFuncAttributeMaxDynamicSharedMemorySize, g1_smem);
    cudaFuncSetAttribute((const void*)hmma_gemm<K2 / 64>,
                         cudaFuncAttributeMaxDynamicSharedMemorySize, g2_smem);

    // 0) weight converts only (x transpose is fused into GEMM1)
    weights_convert<<<QKV_CH + DIMC, 512>>>(Wq, Wkv, Wo, wqkv, wo);

    // 1) qkv projection: D[p][ch] fp16, M=12544, N=1536, K=384, A fused from x
    hmma_gemm_xa<K1 / 64><<<dim3(QKV_CH / 256, NPIX / 128), 256, g1_smem>>>(
        x, wqkv, DIMC, qkvT, QKV_CH);

    // 2) neighborhood attention (warp per pixel-head-pair, fp16 qkv)
    attn_kernel<<<dim3(IMG_W / 2, IMG_H, BATCH), 256>>>(qkvT, aoT);

    // 3) out projection: D[ch][p] -> out (channel-major) + bias, K=512
    hmma_gemm<K2 / 64><<<dim3(NPIX / 256, DIMC / 128), 256, g2_smem>>>(
        wo, K2, aoT, INNER, bo, out);
}